// round 15
// baseline (speedup 1.0000x reference)
#include <cuda_runtime.h>
#include <cuda_bf16.h>
#include <cstdint>

// ---------------------------------------------------------------------------
// Problem constants
// ---------------------------------------------------------------------------
#define K_CODES 1024
#define C_DIM   256
#define HW      4096
#define BATCH   32
#define NPIX    (BATCH*HW)          // 131072
#define QN      (BATCH*C_DIM*HW)    // 8388608

#define TNPIX   64                  // pixels per CTA
#define MARGIN  4e-3f               // >= 2*eps(bf16-hi dot) = 2.4e-3 (provable)
#define SLOTS   16                  // candidate slots per pixel (+ exact fallback)

// Scratch (device globals; no cudaMalloc allowed)
__device__ float g_enorm[K_CODES];
__device__ float g_xnorm[NPIX];
__device__ int   g_idx[NPIX];
__device__ __align__(16) __nv_bfloat16 g_cbbf[K_CODES * C_DIM];
__device__ __align__(16) __nv_bfloat16 g_xbf[(size_t)QN];   // same (b,c,hw) layout as x

// ---------------------------------------------------------------------------
// PTX helpers — plain features only (compute_103-safe)
// ---------------------------------------------------------------------------
__device__ __forceinline__ uint32_t smem_u32(const void* p) {
    uint32_t a;
    asm("{ .reg .u64 t; cvta.to.shared.u64 t, %1; cvt.u32.u64 %0, t; }" : "=r"(a) : "l"(p));
    return a;
}
#define LDSM_X4(r, a) \
    asm volatile("ldmatrix.sync.aligned.m8n8.x4.shared.b16 {%0,%1,%2,%3}, [%4];" \
        : "=r"((r)[0]), "=r"((r)[1]), "=r"((r)[2]), "=r"((r)[3]) : "r"(a))
#define LDSM_X4_T(r, a) \
    asm volatile("ldmatrix.sync.aligned.m8n8.x4.trans.shared.b16 {%0,%1,%2,%3}, [%4];" \
        : "=r"((r)[0]), "=r"((r)[1]), "=r"((r)[2]), "=r"((r)[3]) : "r"(a))
#define MMA_BF16(d, a, b0, b1) \
    asm volatile("mma.sync.aligned.m16n8k16.row.col.f32.bf16.bf16.f32 " \
        "{%0,%1,%2,%3}, {%4,%5,%6,%7}, {%8,%9}, {%0,%1,%2,%3};" \
        : "+f"((d)[0]), "+f"((d)[1]), "+f"((d)[2]), "+f"((d)[3]) \
        : "r"((a)[0]), "r"((a)[1]), "r"((a)[2]), "r"((a)[3]), "r"(b0), "r"(b1))
#define CP_ASYNC16(dst, src) \
    asm volatile("cp.async.cg.shared.global [%0], [%1], 16;" :: "r"(dst), "l"(src))
#define CP_COMMIT() asm volatile("cp.async.commit_group;")
#define CP_WAIT0()  asm volatile("cp.async.wait_group 0;")

__device__ __forceinline__ unsigned long long packkey(float s, int k) {
    unsigned u = __float_as_uint(s);
    u = (u & 0x80000000u) ? ~u : (u | 0x80000000u);
    return ((unsigned long long)u << 32) | (unsigned)k;
}
__device__ __forceinline__ float unpack_score(unsigned long long key) {
    unsigned u = (unsigned)(key >> 32);
    u = (u & 0x80000000u) ? (u & 0x7FFFFFFFu) : ~u;
    return __uint_as_float(u);
}

// ---------------------------------------------------------------------------
// 1) fused prep kernel:
//    [0,8192):      x -> bf16 elementwise (coalesced, same layout)
//    [8192,8448):   cb -> bf16
//    [8448,8452):   codebook row norms (exact)
//    [8452,8964):   per-pixel exact xnorm (reference order, verified)
// ---------------------------------------------------------------------------
__global__ void prep_kernel(const float* __restrict__ x, const float* __restrict__ cb) {
    const int bid = blockIdx.x, tid = threadIdx.x;
    if (bid < 8192) {
        int f = bid * 256 + tid;               // float4 index, 0..2097151
        float4 v = reinterpret_cast<const float4*>(x)[f];
        __nv_bfloat16 b0 = __float2bfloat16(v.x), b1 = __float2bfloat16(v.y);
        __nv_bfloat16 b2 = __float2bfloat16(v.z), b3 = __float2bfloat16(v.w);
        uint32_t lo = ((uint32_t)__bfloat16_as_ushort(b1) << 16) | __bfloat16_as_ushort(b0);
        uint32_t hi = ((uint32_t)__bfloat16_as_ushort(b3) << 16) | __bfloat16_as_ushort(b2);
        reinterpret_cast<uint2*>(g_xbf)[f] = make_uint2(lo, hi);
    } else if (bid < 8448) {
        int f = (bid - 8192) * 256 + tid;      // float4 index, 0..65535
        float4 v = reinterpret_cast<const float4*>(cb)[f];
        __nv_bfloat16 b0 = __float2bfloat16(v.x), b1 = __float2bfloat16(v.y);
        __nv_bfloat16 b2 = __float2bfloat16(v.z), b3 = __float2bfloat16(v.w);
        uint32_t lo = ((uint32_t)__bfloat16_as_ushort(b1) << 16) | __bfloat16_as_ushort(b0);
        uint32_t hi = ((uint32_t)__bfloat16_as_ushort(b3) << 16) | __bfloat16_as_ushort(b2);
        reinterpret_cast<uint2*>(g_cbbf)[f] = make_uint2(lo, hi);
    } else if (bid < 8452) {
        int k = (bid - 8448) * 256 + tid;
        const float4* row = reinterpret_cast<const float4*>(cb + (size_t)k * C_DIM);
        float s = 0.f;
        #pragma unroll
        for (int i = 0; i < C_DIM / 4; i++) {
            float4 v = row[i];
            s += v.x*v.x + v.y*v.y + v.z*v.z + v.w*v.w;
        }
        g_enorm[k] = s;
    } else {
        int p = (bid - 8452) * 256 + tid;
        int b  = p >> 12;
        int hw = p & (HW - 1);
        const float* xb = x + (size_t)b * C_DIM * HW + hw;
        float s = 0.f;
        #pragma unroll 8
        for (int c = 0; c < C_DIM; c++) {
            float v = xb[(size_t)c * HW];
            s = __fadd_rn(s, __fmul_rn(v, v));
        }
        g_xnorm[p] = s;
    }
}

// ---------------------------------------------------------------------------
// 2) fused VQ kernel: bf16 mma (verified fragment mapping / at the 128 MAC/SM/cyc
//    packed-scalar ceiling), cp.async double-buffered cb chunks, per-kt
//    running-min + margin emission, exact fp32-chain recheck (reference
//    bit-semantics), fused idx+gather tail. 2 CTAs/SM.
// ---------------------------------------------------------------------------
#define XBF_ROW   144              // bytes per c-row (128 data + 16 pad) — verified
#define CB_ROW    80               // bytes per code row per 32-c chunk — verified
#define CB_BUF    20480            // 256 rows * 80
#define OFF_XBF   0                // 256*144 = 36864
#define OFF_CB    36864            // 2*20480 = 40960
#define OFF_EN    77824            // 4096
#define OFF_XN    81920            // 256
#define OFF_BEST  82176            // 512
#define OFF_BESTE 82688            // 512
#define OFF_CNT   83200            // 256
#define OFF_CAND  83456            // 64*16*4 = 4096
#define SMEM_TOTAL 87552

__global__ __launch_bounds__(256, 2)
void vq_mma_kernel(const float* __restrict__ x, const float* __restrict__ cb,
                   float* __restrict__ outf, float* __restrict__ outq, int fused_out) {
    extern __shared__ char smem[];
    const uint32_t sb = smem_u32(smem);
    const int tid = threadIdx.x, wid = tid >> 5, lane = tid & 31;
    const int p0 = blockIdx.x * TNPIX;
    const int bb = p0 >> 12;
    const int hw0 = p0 & (HW - 1);

    float* en_s = reinterpret_cast<float*>(smem + OFF_EN);
    float* xn_s = reinterpret_cast<float*>(smem + OFF_XN);
    unsigned long long* best  = reinterpret_cast<unsigned long long*>(smem + OFF_BEST);
    unsigned long long* beste = reinterpret_cast<unsigned long long*>(smem + OFF_BESTE);
    int* cnt_px = reinterpret_cast<int*>(smem + OFF_CNT);
    unsigned* cand = reinterpret_cast<unsigned*>(smem + OFF_CAND);

    // XBF tile: 256 c-rows x 64 px bf16 (128B/row) via cp.async
    {
        const char* xbytes = reinterpret_cast<const char*>(g_xbf)
                           + ((size_t)bb * C_DIM * HW + hw0) * 2;
        #pragma unroll
        for (int i = 0; i < 8; i++) {
            int f = tid + i * 256;             // 0..2047
            int c = f >> 3, seg = f & 7;
            CP_ASYNC16(sb + OFF_XBF + c * XBF_ROW + seg * 16,
                       xbytes + (size_t)c * (HW * 2) + seg * 16);
        }
        CP_COMMIT();
    }
    // CB chunk 0 (256 codes x 32 c)
    {
        const char* cbytes = reinterpret_cast<const char*>(g_cbbf);
        #pragma unroll
        for (int i = 0; i < 4; i++) {
            int f = tid + i * 256;             // 0..1023
            int row = f >> 2, seg = f & 3;
            CP_ASYNC16(sb + OFF_CB + row * CB_ROW + seg * 16,
                       cbytes + (size_t)row * 512 + seg * 16);
        }
        CP_COMMIT();
    }

    if (tid < TNPIX) {
        xn_s[tid]  = g_xnorm[p0 + tid];
        best[tid]  = 0xFFFFFFFFFFFFFFFFULL;
        beste[tid] = 0xFFFFFFFFFFFFFFFFULL;
        cnt_px[tid] = 0;
    }
    for (int i = tid; i < K_CODES; i += 256) en_s[i] = g_enorm[i];

    const uint32_t a_rowsel = (uint32_t)(lane & 15);
    const uint32_t a_half   = (uint32_t)(lane >> 4);

    float acc[2][8][4];

    // 32 chunk-steps: kt = g>>3 (256-code stage), cc = g&7 (32-c slice)
    for (int g = 0; g < 32; g++) {
        const int buf = g & 1;
        CP_WAIT0();
        __syncthreads();     // chunk g (+XBF at g=0) visible; buf^1 free

        if (g < 31) {        // prefetch chunk g+1 into other buffer
            int gn = g + 1;
            int ktn = gn >> 3, ccn_ = gn & 7;
            const char* srcb = reinterpret_cast<const char*>(g_cbbf)
                             + (size_t)(ktn * 256) * 512 + ccn_ * 64;
            uint32_t dbase = sb + OFF_CB + (buf ^ 1) * CB_BUF;
            #pragma unroll
            for (int i = 0; i < 4; i++) {
                int f = tid + i * 256;
                int row = f >> 2, seg = f & 3;
                CP_ASYNC16(dbase + row * CB_ROW + seg * 16,
                           srcb + (size_t)row * 512 + seg * 16);
            }
            CP_COMMIT();
        }

        const int cc = g & 7;
        if (cc == 0) {
            #pragma unroll
            for (int m = 0; m < 2; m++)
                #pragma unroll
                for (int n = 0; n < 8; n++)
                    #pragma unroll
                    for (int j = 0; j < 4; j++) acc[m][n][j] = 0.f;
        }

        const uint32_t abase = sb + OFF_CB + buf * CB_BUF;
        #pragma unroll
        for (int ccn = 0; ccn < 2; ccn++) {
            uint32_t a[2][4], bfr[4][4];
            #pragma unroll
            for (int m = 0; m < 2; m++) {
                uint32_t addr = abase + (wid * 32 + m * 16 + a_rowsel) * CB_ROW
                              + ccn * 32 + a_half * 16;
                LDSM_X4(a[m], addr);
            }
            #pragma unroll
            for (int np = 0; np < 4; np++) {
                uint32_t addr = sb + OFF_XBF + (cc * 32 + ccn * 16 + a_rowsel) * XBF_ROW
                              + (np * 16 + a_half * 8) * 2;
                LDSM_X4_T(bfr[np], addr);
            }
            #pragma unroll
            for (int m = 0; m < 2; m++)
                #pragma unroll
                for (int n = 0; n < 8; n++)
                    MMA_BF16(acc[m][n], a[m], bfr[n >> 1][(n & 1) * 2], bfr[n >> 1][(n & 1) * 2 + 1]);
        }

        if (cc == 7) {   // stage epilogue: 256 codes scored
            const int kt = g >> 3;
            // running-min: thread min -> reduce over code-rows -> atomicMin
            #pragma unroll
            for (int n = 0; n < 8; n++)
                #pragma unroll
                for (int co = 0; co < 2; co++) {
                    int px = n * 8 + (lane & 3) * 2 + co;
                    float xn = xn_s[px];
                    unsigned long long kk = 0xFFFFFFFFFFFFFFFFULL;
                    #pragma unroll
                    for (int m = 0; m < 2; m++)
                        #pragma unroll
                        for (int rr = 0; rr < 2; rr++) {
                            int code = kt * 256 + wid * 32 + m * 16 + (lane >> 2) + rr * 8;
                            float s = __fsub_rn(__fadd_rn(xn, en_s[code]),
                                                __fmul_rn(2.f, acc[m][n][rr * 2 + co]));
                            unsigned long long k2 = packkey(s, code);
                            if (k2 < kk) kk = k2;
                        }
                    #pragma unroll
                    for (int d = 4; d < 32; d <<= 1) {
                        unsigned long long o = __shfl_xor_sync(0xFFFFFFFFu, kk, d);
                        if (o < kk) kk = o;
                    }
                    if ((lane >> 2) == 0) atomicMin(&best[px], kk);
                }
            __syncthreads();
            // candidate emission vs running min + margin (superset of winners)
            #pragma unroll
            for (int n = 0; n < 8; n++)
                #pragma unroll
                for (int co = 0; co < 2; co++) {
                    int px = n * 8 + (lane & 3) * 2 + co;
                    float thr = unpack_score(best[px]) + MARGIN;
                    float xn = xn_s[px];
                    #pragma unroll
                    for (int m = 0; m < 2; m++)
                        #pragma unroll
                        for (int rr = 0; rr < 2; rr++) {
                            int code = kt * 256 + wid * 32 + m * 16 + (lane >> 2) + rr * 8;
                            float s = __fsub_rn(__fadd_rn(xn, en_s[code]),
                                                __fmul_rn(2.f, acc[m][n][rr * 2 + co]));
                            if (s <= thr) {
                                int slot = atomicAdd(&cnt_px[px], 1);
                                if (slot < SLOTS) cand[px * SLOTS + slot] = (unsigned)code;
                            }
                        }
                }
        }
    }
    __syncthreads();

    // ---- exact recheck: sequential fp32 FMA chain, c ascending (reference order)
    for (int idx = tid; idx < TNPIX * SLOTS; idx += 256) {
        int px = idx / SLOTS, sl = idx - px * SLOTS;
        int nc = cnt_px[px]; if (nc > SLOTS) nc = SLOTS;
        if (sl < nc) {
            int k = (int)cand[idx];
            const float* xp = x + (size_t)bb * C_DIM * HW + (hw0 + px);
            const float* ck = cb + (size_t)k * C_DIM;
            float dot = 0.f;
            #pragma unroll 8
            for (int c = 0; c < C_DIM; c++)
                dot = __fmaf_rn(ck[c], xp[(size_t)c * HW], dot);
            float s = __fsub_rn(__fadd_rn(xn_s[px], en_s[k]), __fmul_rn(2.f, dot));
            atomicMin(&beste[px], packkey(s, k));
        }
    }
    __syncthreads();
    // overflow fallback (provably safe; rare at SLOTS=16)
    for (int px = 0; px < TNPIX; px++) {
        if (cnt_px[px] > SLOTS) {
            const float* xp = x + (size_t)bb * C_DIM * HW + (hw0 + px);
            for (int k = tid; k < K_CODES; k += 256) {
                const float* ck = cb + (size_t)k * C_DIM;
                float dot = 0.f;
                #pragma unroll 8
                for (int c = 0; c < C_DIM; c++)
                    dot = __fmaf_rn(ck[c], xp[(size_t)c * HW], dot);
                float s = __fsub_rn(__fadd_rn(xn_s[px], en_s[k]), __fmul_rn(2.f, dot));
                atomicMin(&beste[px], packkey(s, k));
            }
        }
    }
    __syncthreads();
    if (tid < TNPIX) g_idx[p0 + tid] = (int)(beste[tid] & 0xFFFFFFFFu);

    // ---- fused outputs (concat mode): idx-as-float + quantized gather
    if (fused_out) {
        if (tid < TNPIX)
            outf[p0 + tid] = (float)(int)(beste[tid] & 0xFFFFFFFFu);
        int px = tid & 63, cg = tid >> 6;          // 4 c-groups of 64
        int k = (int)(beste[px] & 0xFFFFFFFFu);
        const float* ck = cb + (size_t)k * C_DIM + cg * 64;
        float* ob = outq + ((size_t)bb * C_DIM + cg * 64) * HW + hw0 + px;
        #pragma unroll 8
        for (int c = 0; c < 64; c++)
            ob[(size_t)c * HW] = __ldg(ck + c);
    }
}

// ---------------------------------------------------------------------------
// 3) standalone outputs for non-concat modes (verified)
// ---------------------------------------------------------------------------
__global__ void gather_kernel(const float* __restrict__ cb, float* __restrict__ q) {
    long long o4 = (long long)blockIdx.x * blockDim.x + threadIdx.x;
    if (o4 >= (long long)(QN / 4)) return;
    int hw = (int)(o4 & (HW - 1));
    long long t = o4 >> 12;
    int c4 = (int)(t & 63);
    int b  = (int)(t >> 6);
    int k = g_idx[b * HW + hw];
    float4 v = __ldg(reinterpret_cast<const float4*>(cb) + (size_t)k * 64 + c4);
    float* qb = q + ((size_t)b * C_DIM + c4 * 4) * HW + hw;
    qb[0]      = v.x;
    qb[HW]     = v.y;
    qb[2 * HW] = v.z;
    qb[3 * HW] = v.w;
}
__global__ void idxi_kernel(int* __restrict__ out) {
    int n = blockIdx.x * blockDim.x + threadIdx.x;
    if (n < NPIX) out[n] = g_idx[n];
}

// ---------------------------------------------------------------------------
extern "C" void kernel_launch(void* const* d_in, const int* in_sizes, int n_in,
                              void* d_out, int out_size) {
    const float* x  = (const float*)d_in[0];   // (32,256,64,64) f32
    const float* cb = (const float*)d_in[1];   // (1024,256) f32

    cudaFuncSetAttribute(vq_mma_kernel,
                         cudaFuncAttributeMaxDynamicSharedMemorySize, SMEM_TOTAL);

    prep_kernel<<<8964, 256>>>(x, cb);

    if (out_size >= NPIX + QN) {
        vq_mma_kernel<<<NPIX / TNPIX, 256, SMEM_TOTAL>>>(
            x, cb, (float*)d_out, (float*)d_out + NPIX, 1);
    } else if (out_size >= QN) {
        vq_mma_kernel<<<NPIX / TNPIX, 256, SMEM_TOTAL>>>(x, cb, nullptr, nullptr, 0);
        gather_kernel<<<QN / 4 / 256, 256>>>(cb, (float*)d_out);
    } else {
        vq_mma_kernel<<<NPIX / TNPIX, 256, SMEM_TOTAL>>>(x, cb, nullptr, nullptr, 0);
        idxi_kernel<<<NPIX / 256, 256>>>((int*)d_out);
    }
}

// round 16
// speedup vs baseline: 72.1244x; 72.1244x over previous
#include <cuda_runtime.h>
#include <cuda_bf16.h>
#include <cstdint>

// ---------------------------------------------------------------------------
// Problem constants
// ---------------------------------------------------------------------------
#define K_CODES 1024
#define C_DIM   256
#define HW      4096
#define BATCH   32
#define NPIX    (BATCH*HW)          // 131072
#define QN      (BATCH*C_DIM*HW)    // 33554432  (NOT 8.4M — round-15 bug)

#define TNPIX   64                  // pixels per CTA
#define MARGIN  4e-3f               // >= 2*eps(bf16-hi dot) = 2.4e-3 (provable)
#define SLOTS   16                  // candidate slots per pixel (+ exact fallback)

// Scratch (device globals; no cudaMalloc allowed)
__device__ float g_enorm[K_CODES];
__device__ float g_xnorm[NPIX];
__device__ int   g_idx[NPIX];
__device__ __align__(16) __nv_bfloat16 g_cbbf[K_CODES * C_DIM];
__device__ __align__(16) __nv_bfloat16 g_xbf[(size_t)QN];   // same (b,c,hw) layout as x

// ---------------------------------------------------------------------------
// PTX helpers — plain features only (compute_103-safe)
// ---------------------------------------------------------------------------
__device__ __forceinline__ uint32_t smem_u32(const void* p) {
    uint32_t a;
    asm("{ .reg .u64 t; cvta.to.shared.u64 t, %1; cvt.u32.u64 %0, t; }" : "=r"(a) : "l"(p));
    return a;
}
#define LDSM_X4(r, a) \
    asm volatile("ldmatrix.sync.aligned.m8n8.x4.shared.b16 {%0,%1,%2,%3}, [%4];" \
        : "=r"((r)[0]), "=r"((r)[1]), "=r"((r)[2]), "=r"((r)[3]) : "r"(a))
#define LDSM_X4_T(r, a) \
    asm volatile("ldmatrix.sync.aligned.m8n8.x4.trans.shared.b16 {%0,%1,%2,%3}, [%4];" \
        : "=r"((r)[0]), "=r"((r)[1]), "=r"((r)[2]), "=r"((r)[3]) : "r"(a))
#define MMA_BF16(d, a, b0, b1) \
    asm volatile("mma.sync.aligned.m16n8k16.row.col.f32.bf16.bf16.f32 " \
        "{%0,%1,%2,%3}, {%4,%5,%6,%7}, {%8,%9}, {%0,%1,%2,%3};" \
        : "+f"((d)[0]), "+f"((d)[1]), "+f"((d)[2]), "+f"((d)[3]) \
        : "r"((a)[0]), "r"((a)[1]), "r"((a)[2]), "r"((a)[3]), "r"(b0), "r"(b1))
#define CP_ASYNC16(dst, src) \
    asm volatile("cp.async.cg.shared.global [%0], [%1], 16;" :: "r"(dst), "l"(src))
#define CP_COMMIT() asm volatile("cp.async.commit_group;")
#define CP_WAIT0()  asm volatile("cp.async.wait_group 0;")

__device__ __forceinline__ unsigned long long packkey(float s, int k) {
    unsigned u = __float_as_uint(s);
    u = (u & 0x80000000u) ? ~u : (u | 0x80000000u);
    return ((unsigned long long)u << 32) | (unsigned)k;
}
__device__ __forceinline__ float unpack_score(unsigned long long key) {
    unsigned u = (unsigned)(key >> 32);
    u = (u & 0x80000000u) ? (u & 0x7FFFFFFFu) : ~u;
    return __uint_as_float(u);
}

// ---------------------------------------------------------------------------
// 1) fused prep kernel — grid 33540:
//    [0,32768):       x -> bf16 elementwise (ALL of x this time: QN/4 float4s)
//    [32768,33024):   cb -> bf16
//    [33024,33028):   codebook row norms (exact)
//    [33028,33540):   per-pixel exact xnorm (reference order, verified)
// ---------------------------------------------------------------------------
#define PREP_XBLK 32768
__global__ void prep_kernel(const float* __restrict__ x, const float* __restrict__ cb) {
    const int bid = blockIdx.x, tid = threadIdx.x;
    if (bid < PREP_XBLK) {
        int f = bid * 256 + tid;               // float4 index, 0..QN/4-1
        float4 v = reinterpret_cast<const float4*>(x)[f];
        __nv_bfloat16 b0 = __float2bfloat16(v.x), b1 = __float2bfloat16(v.y);
        __nv_bfloat16 b2 = __float2bfloat16(v.z), b3 = __float2bfloat16(v.w);
        uint32_t lo = ((uint32_t)__bfloat16_as_ushort(b1) << 16) | __bfloat16_as_ushort(b0);
        uint32_t hi = ((uint32_t)__bfloat16_as_ushort(b3) << 16) | __bfloat16_as_ushort(b2);
        reinterpret_cast<uint2*>(g_xbf)[f] = make_uint2(lo, hi);
    } else if (bid < PREP_XBLK + 256) {
        int f = (bid - PREP_XBLK) * 256 + tid; // float4 index, 0..65535
        float4 v = reinterpret_cast<const float4*>(cb)[f];
        __nv_bfloat16 b0 = __float2bfloat16(v.x), b1 = __float2bfloat16(v.y);
        __nv_bfloat16 b2 = __float2bfloat16(v.z), b3 = __float2bfloat16(v.w);
        uint32_t lo = ((uint32_t)__bfloat16_as_ushort(b1) << 16) | __bfloat16_as_ushort(b0);
        uint32_t hi = ((uint32_t)__bfloat16_as_ushort(b3) << 16) | __bfloat16_as_ushort(b2);
        reinterpret_cast<uint2*>(g_cbbf)[f] = make_uint2(lo, hi);
    } else if (bid < PREP_XBLK + 260) {
        int k = (bid - PREP_XBLK - 256) * 256 + tid;
        const float4* row = reinterpret_cast<const float4*>(cb + (size_t)k * C_DIM);
        float s = 0.f;
        #pragma unroll
        for (int i = 0; i < C_DIM / 4; i++) {
            float4 v = row[i];
            s += v.x*v.x + v.y*v.y + v.z*v.z + v.w*v.w;
        }
        g_enorm[k] = s;
    } else {
        int p = (bid - PREP_XBLK - 260) * 256 + tid;
        int b  = p >> 12;
        int hw = p & (HW - 1);
        const float* xb = x + (size_t)b * C_DIM * HW + hw;
        float s = 0.f;
        #pragma unroll 8
        for (int c = 0; c < C_DIM; c++) {
            float v = xb[(size_t)c * HW];
            s = __fadd_rn(s, __fmul_rn(v, v));
        }
        g_xnorm[p] = s;
    }
}

// ---------------------------------------------------------------------------
// 2) fused VQ kernel: bf16 mma (verified mapping; at the 128 MAC/SM/cyc
//    packed-scalar ceiling), cp.async double-buffered cb chunks, per-kt
//    running-min + margin emission, exact fp32-chain recheck (reference
//    bit-semantics), fused idx+gather tail. 2 CTAs/SM.
// ---------------------------------------------------------------------------
#define XBF_ROW   144              // bytes per c-row (128 data + 16 pad) — verified
#define CB_ROW    80               // bytes per code row per 32-c chunk — verified
#define CB_BUF    20480            // 256 rows * 80
#define OFF_XBF   0                // 256*144 = 36864
#define OFF_CB    36864            // 2*20480 = 40960
#define OFF_EN    77824            // 4096
#define OFF_XN    81920            // 256
#define OFF_BEST  82176            // 512
#define OFF_BESTE 82688            // 512
#define OFF_CNT   83200            // 256
#define OFF_CAND  83456            // 64*16*4 = 4096
#define SMEM_TOTAL 87552

__global__ __launch_bounds__(256, 2)
void vq_mma_kernel(const float* __restrict__ x, const float* __restrict__ cb,
                   float* __restrict__ outf, float* __restrict__ outq, int fused_out) {
    extern __shared__ char smem[];
    const uint32_t sb = smem_u32(smem);
    const int tid = threadIdx.x, wid = tid >> 5, lane = tid & 31;
    const int p0 = blockIdx.x * TNPIX;
    const int bb = p0 >> 12;
    const int hw0 = p0 & (HW - 1);

    float* en_s = reinterpret_cast<float*>(smem + OFF_EN);
    float* xn_s = reinterpret_cast<float*>(smem + OFF_XN);
    unsigned long long* best  = reinterpret_cast<unsigned long long*>(smem + OFF_BEST);
    unsigned long long* beste = reinterpret_cast<unsigned long long*>(smem + OFF_BESTE);
    int* cnt_px = reinterpret_cast<int*>(smem + OFF_CNT);
    unsigned* cand = reinterpret_cast<unsigned*>(smem + OFF_CAND);

    // XBF tile: 256 c-rows x 64 px bf16 (128B/row) via cp.async
    {
        const char* xbytes = reinterpret_cast<const char*>(g_xbf)
                           + ((size_t)bb * C_DIM * HW + hw0) * 2;
        #pragma unroll
        for (int i = 0; i < 8; i++) {
            int f = tid + i * 256;             // 0..2047
            int c = f >> 3, seg = f & 7;
            CP_ASYNC16(sb + OFF_XBF + c * XBF_ROW + seg * 16,
                       xbytes + (size_t)c * (HW * 2) + seg * 16);
        }
        CP_COMMIT();
    }
    // CB chunk 0 (256 codes x 32 c)
    {
        const char* cbytes = reinterpret_cast<const char*>(g_cbbf);
        #pragma unroll
        for (int i = 0; i < 4; i++) {
            int f = tid + i * 256;             // 0..1023
            int row = f >> 2, seg = f & 3;
            CP_ASYNC16(sb + OFF_CB + row * CB_ROW + seg * 16,
                       cbytes + (size_t)row * 512 + seg * 16);
        }
        CP_COMMIT();
    }

    if (tid < TNPIX) {
        xn_s[tid]  = g_xnorm[p0 + tid];
        best[tid]  = 0xFFFFFFFFFFFFFFFFULL;
        beste[tid] = 0xFFFFFFFFFFFFFFFFULL;
        cnt_px[tid] = 0;
    }
    for (int i = tid; i < K_CODES; i += 256) en_s[i] = g_enorm[i];

    const uint32_t a_rowsel = (uint32_t)(lane & 15);
    const uint32_t a_half   = (uint32_t)(lane >> 4);

    float acc[2][8][4];

    // 32 chunk-steps: kt = g>>3 (256-code stage), cc = g&7 (32-c slice)
    for (int g = 0; g < 32; g++) {
        const int buf = g & 1;
        CP_WAIT0();
        __syncthreads();     // chunk g (+XBF at g=0) visible; buf^1 free

        if (g < 31) {        // prefetch chunk g+1 into other buffer
            int gn = g + 1;
            int ktn = gn >> 3, ccn_ = gn & 7;
            const char* srcb = reinterpret_cast<const char*>(g_cbbf)
                             + (size_t)(ktn * 256) * 512 + ccn_ * 64;
            uint32_t dbase = sb + OFF_CB + (buf ^ 1) * CB_BUF;
            #pragma unroll
            for (int i = 0; i < 4; i++) {
                int f = tid + i * 256;
                int row = f >> 2, seg = f & 3;
                CP_ASYNC16(dbase + row * CB_ROW + seg * 16,
                           srcb + (size_t)row * 512 + seg * 16);
            }
            CP_COMMIT();
        }

        const int cc = g & 7;
        if (cc == 0) {
            #pragma unroll
            for (int m = 0; m < 2; m++)
                #pragma unroll
                for (int n = 0; n < 8; n++)
                    #pragma unroll
                    for (int j = 0; j < 4; j++) acc[m][n][j] = 0.f;
        }

        const uint32_t abase = sb + OFF_CB + buf * CB_BUF;
        #pragma unroll
        for (int ccn = 0; ccn < 2; ccn++) {
            uint32_t a[2][4], bfr[4][4];
            #pragma unroll
            for (int m = 0; m < 2; m++) {
                uint32_t addr = abase + (wid * 32 + m * 16 + a_rowsel) * CB_ROW
                              + ccn * 32 + a_half * 16;
                LDSM_X4(a[m], addr);
            }
            #pragma unroll
            for (int np = 0; np < 4; np++) {
                uint32_t addr = sb + OFF_XBF + (cc * 32 + ccn * 16 + a_rowsel) * XBF_ROW
                              + (np * 16 + a_half * 8) * 2;
                LDSM_X4_T(bfr[np], addr);
            }
            #pragma unroll
            for (int m = 0; m < 2; m++)
                #pragma unroll
                for (int n = 0; n < 8; n++)
                    MMA_BF16(acc[m][n], a[m], bfr[n >> 1][(n & 1) * 2], bfr[n >> 1][(n & 1) * 2 + 1]);
        }

        if (cc == 7) {   // stage epilogue: 256 codes scored
            const int kt = g >> 3;
            // running-min: thread min -> reduce over code-rows -> atomicMin
            #pragma unroll
            for (int n = 0; n < 8; n++)
                #pragma unroll
                for (int co = 0; co < 2; co++) {
                    int px = n * 8 + (lane & 3) * 2 + co;
                    float xn = xn_s[px];
                    unsigned long long kk = 0xFFFFFFFFFFFFFFFFULL;
                    #pragma unroll
                    for (int m = 0; m < 2; m++)
                        #pragma unroll
                        for (int rr = 0; rr < 2; rr++) {
                            int code = kt * 256 + wid * 32 + m * 16 + (lane >> 2) + rr * 8;
                            float s = __fsub_rn(__fadd_rn(xn, en_s[code]),
                                                __fmul_rn(2.f, acc[m][n][rr * 2 + co]));
                            unsigned long long k2 = packkey(s, code);
                            if (k2 < kk) kk = k2;
                        }
                    #pragma unroll
                    for (int d = 4; d < 32; d <<= 1) {
                        unsigned long long o = __shfl_xor_sync(0xFFFFFFFFu, kk, d);
                        if (o < kk) kk = o;
                    }
                    if ((lane >> 2) == 0) atomicMin(&best[px], kk);
                }
            __syncthreads();
            // candidate emission vs running min + margin (superset of winners)
            #pragma unroll
            for (int n = 0; n < 8; n++)
                #pragma unroll
                for (int co = 0; co < 2; co++) {
                    int px = n * 8 + (lane & 3) * 2 + co;
                    float thr = unpack_score(best[px]) + MARGIN;
                    float xn = xn_s[px];
                    #pragma unroll
                    for (int m = 0; m < 2; m++)
                        #pragma unroll
                        for (int rr = 0; rr < 2; rr++) {
                            int code = kt * 256 + wid * 32 + m * 16 + (lane >> 2) + rr * 8;
                            float s = __fsub_rn(__fadd_rn(xn, en_s[code]),
                                                __fmul_rn(2.f, acc[m][n][rr * 2 + co]));
                            if (s <= thr) {
                                int slot = atomicAdd(&cnt_px[px], 1);
                                if (slot < SLOTS) cand[px * SLOTS + slot] = (unsigned)code;
                            }
                        }
                }
        }
    }
    __syncthreads();

    // ---- exact recheck: sequential fp32 FMA chain, c ascending (reference order)
    for (int idx = tid; idx < TNPIX * SLOTS; idx += 256) {
        int px = idx / SLOTS, sl = idx - px * SLOTS;
        int nc = cnt_px[px]; if (nc > SLOTS) nc = SLOTS;
        if (sl < nc) {
            int k = (int)cand[idx];
            const float* xp = x + (size_t)bb * C_DIM * HW + (hw0 + px);
            const float* ck = cb + (size_t)k * C_DIM;
            float dot = 0.f;
            #pragma unroll 8
            for (int c = 0; c < C_DIM; c++)
                dot = __fmaf_rn(ck[c], xp[(size_t)c * HW], dot);
            float s = __fsub_rn(__fadd_rn(xn_s[px], en_s[k]), __fmul_rn(2.f, dot));
            atomicMin(&beste[px], packkey(s, k));
        }
    }
    __syncthreads();
    // overflow fallback (provably safe; rare at SLOTS=16)
    for (int px = 0; px < TNPIX; px++) {
        if (cnt_px[px] > SLOTS) {
            const float* xp = x + (size_t)bb * C_DIM * HW + (hw0 + px);
            for (int k = tid; k < K_CODES; k += 256) {
                const float* ck = cb + (size_t)k * C_DIM;
                float dot = 0.f;
                #pragma unroll 8
                for (int c = 0; c < C_DIM; c++)
                    dot = __fmaf_rn(ck[c], xp[(size_t)c * HW], dot);
                float s = __fsub_rn(__fadd_rn(xn_s[px], en_s[k]), __fmul_rn(2.f, dot));
                atomicMin(&beste[px], packkey(s, k));
            }
        }
    }
    __syncthreads();
    if (tid < TNPIX) g_idx[p0 + tid] = (int)(beste[tid] & 0xFFFFFFFFu);

    // ---- fused outputs (concat mode): idx-as-float + quantized gather
    if (fused_out) {
        if (tid < TNPIX)
            outf[p0 + tid] = (float)(int)(beste[tid] & 0xFFFFFFFFu);
        int px = tid & 63, cg = tid >> 6;          // 4 c-groups of 64
        int k = (int)(beste[px] & 0xFFFFFFFFu);
        const float* ck = cb + (size_t)k * C_DIM + cg * 64;
        float* ob = outq + ((size_t)bb * C_DIM + cg * 64) * HW + hw0 + px;
        #pragma unroll 8
        for (int c = 0; c < 64; c++)
            ob[(size_t)c * HW] = __ldg(ck + c);
    }
}

// ---------------------------------------------------------------------------
// 3) standalone outputs for non-concat modes (verified)
// ---------------------------------------------------------------------------
__global__ void gather_kernel(const float* __restrict__ cb, float* __restrict__ q) {
    long long o4 = (long long)blockIdx.x * blockDim.x + threadIdx.x;
    if (o4 >= (long long)(QN / 4)) return;
    int hw = (int)(o4 & (HW - 1));
    long long t = o4 >> 12;
    int c4 = (int)(t & 63);
    int b  = (int)(t >> 6);
    int k = g_idx[b * HW + hw];
    float4 v = __ldg(reinterpret_cast<const float4*>(cb) + (size_t)k * 64 + c4);
    float* qb = q + ((size_t)b * C_DIM + c4 * 4) * HW + hw;
    qb[0]      = v.x;
    qb[HW]     = v.y;
    qb[2 * HW] = v.z;
    qb[3 * HW] = v.w;
}
__global__ void idxi_kernel(int* __restrict__ out) {
    int n = blockIdx.x * blockDim.x + threadIdx.x;
    if (n < NPIX) out[n] = g_idx[n];
}

// ---------------------------------------------------------------------------
extern "C" void kernel_launch(void* const* d_in, const int* in_sizes, int n_in,
                              void* d_out, int out_size) {
    const float* x  = (const float*)d_in[0];   // (32,256,64,64) f32
    const float* cb = (const float*)d_in[1];   // (1024,256) f32

    cudaFuncSetAttribute(vq_mma_kernel,
                         cudaFuncAttributeMaxDynamicSharedMemorySize, SMEM_TOTAL);

    prep_kernel<<<PREP_XBLK + 256 + 4 + NPIX / 256, 256>>>(x, cb);

    if (out_size >= NPIX + QN) {
        vq_mma_kernel<<<NPIX / TNPIX, 256, SMEM_TOTAL>>>(
            x, cb, (float*)d_out, (float*)d_out + NPIX, 1);
    } else if (out_size >= QN) {
        vq_mma_kernel<<<NPIX / TNPIX, 256, SMEM_TOTAL>>>(x, cb, nullptr, nullptr, 0);
        gather_kernel<<<QN / 4 / 256, 256>>>(cb, (float*)d_out);
    } else {
        vq_mma_kernel<<<NPIX / TNPIX, 256, SMEM_TOTAL>>>(x, cb, nullptr, nullptr, 0);
        idxi_kernel<<<NPIX / 256, 256>>>((int*)d_out);
    }
}

// round 17
// speedup vs baseline: 86.0125x; 1.1926x over previous
#include <cuda_runtime.h>
#include <cuda_bf16.h>
#include <cstdint>

// ---------------------------------------------------------------------------
// Problem constants
// ---------------------------------------------------------------------------
#define K_CODES 1024
#define C_DIM   256
#define HW      4096
#define BATCH   32
#define NPIX    (BATCH*HW)          // 131072
#define QN      (BATCH*C_DIM*HW)    // 33554432 quantized elements

#define TNPIX   64                  // pixels per CTA
#define MARGIN  4e-3f
#define CAND_CAP 3072

// Scratch (device globals; no cudaMalloc allowed)
__device__ float g_enorm[K_CODES];
__device__ int   g_idx[NPIX];
__device__ __nv_bfloat16 g_cbhi[K_CODES * C_DIM];

// ---------------------------------------------------------------------------
// PTX helpers — plain features only (compute_103-safe)
// ---------------------------------------------------------------------------
__device__ __forceinline__ uint32_t smem_u32(const void* p) {
    uint32_t a;
    asm("{ .reg .u64 t; cvta.to.shared.u64 t, %1; cvt.u32.u64 %0, t; }" : "=r"(a) : "l"(p));
    return a;
}
#define LDSM_X4(r, a) \
    asm volatile("ldmatrix.sync.aligned.m8n8.x4.shared.b16 {%0,%1,%2,%3}, [%4];" \
        : "=r"((r)[0]), "=r"((r)[1]), "=r"((r)[2]), "=r"((r)[3]) : "r"(a))
#define LDSM_X4_T(r, a) \
    asm volatile("ldmatrix.sync.aligned.m8n8.x4.trans.shared.b16 {%0,%1,%2,%3}, [%4];" \
        : "=r"((r)[0]), "=r"((r)[1]), "=r"((r)[2]), "=r"((r)[3]) : "r"(a))
#define MMA_BF16(d, a, b0, b1) \
    asm volatile("mma.sync.aligned.m16n8k16.row.col.f32.bf16.bf16.f32 " \
        "{%0,%1,%2,%3}, {%4,%5,%6,%7}, {%8,%9}, {%0,%1,%2,%3};" \
        : "+f"((d)[0]), "+f"((d)[1]), "+f"((d)[2]), "+f"((d)[3]) \
        : "r"((a)[0]), "r"((a)[1]), "r"((a)[2]), "r"((a)[3]), "r"(b0), "r"(b1))
#define CP_ASYNC16(dst, src) \
    asm volatile("cp.async.cg.shared.global [%0], [%1], 16;" :: "r"(dst), "l"(src))
#define CP_COMMIT() asm volatile("cp.async.commit_group;")
#define CP_WAIT(n)  asm volatile("cp.async.wait_group %0;" :: "n"(n))

__device__ __forceinline__ unsigned long long packkey(float s, int k) {
    unsigned u = __float_as_uint(s);
    u = (u & 0x80000000u) ? ~u : (u | 0x80000000u);
    return ((unsigned long long)u << 32) | (unsigned)k;
}
__device__ __forceinline__ float unpack_score(unsigned long long key) {
    unsigned u = (unsigned)(key >> 32);
    u = (u & 0x80000000u) ? (u & 0x7FFFFFFFu) : ~u;
    return __uint_as_float(u);
}

// ---------------------------------------------------------------------------
// 1) merged prep: [0,1024) cb->bf16, [1024,1028) codebook row norms (exact)
// ---------------------------------------------------------------------------
__global__ void prep_kernel(const float* __restrict__ cb) {
    const int bid = blockIdx.x, tid = threadIdx.x;
    if (bid < 1024) {
        int f = bid * 256 + tid;
        g_cbhi[f] = __float2bfloat16(cb[f]);
    } else {
        int k = (bid - 1024) * 256 + tid;
        const float4* row = reinterpret_cast<const float4*>(cb + (size_t)k * C_DIM);
        float s = 0.f;
        #pragma unroll
        for (int i = 0; i < C_DIM / 4; i++) {
            float4 v = row[i];
            s += v.x*v.x + v.y*v.y + v.z*v.z + v.w*v.w;
        }
        g_enorm[k] = s;
    }
}

// ---------------------------------------------------------------------------
// 2) fused VQ kernel — round-7 core BYTE-IDENTICAL (best measured: 66cyc/MMA
//    slot, 1 CTA/SM, 64x64 warp tiles, cp.async double-buffered cb chunks,
//    recheck from smem xf) + fused output tail (r16-verified pattern).
// ---------------------------------------------------------------------------
#define XF_STRIDE  68              // floats (272B/row, 16B aligned)
#define CB_ROW     80              // bytes per 32-c cb chunk row (bank-phase spread)
#define CB_BUF     40960           // 512 rows * 80B
#define OFF_XF    0                // 69632
#define OFF_XBF   69632            // 256*144 = 36864
#define OFF_CB    106496           // 2*40960 = 81920
#define OFF_EN    188416           // 4096
#define OFF_XN    192512           // 256
#define OFF_BEST  192768           // 512
#define OFF_BESTE 193280           // 512
#define OFF_CNT   193792           // 16
#define OFF_CAND  193808           // 12288
#define SMEM_TOTAL 206096

__global__ __launch_bounds__(256, 1)
void vq_hmma_kernel(const float* __restrict__ x, const float* __restrict__ cb,
                    float* __restrict__ outf, float* __restrict__ outq, int fused_out) {
    extern __shared__ char smem[];
    const uint32_t sb = smem_u32(smem);
    const int tid = threadIdx.x, wid = tid >> 5, lane = tid & 31;
    const int p0 = blockIdx.x * TNPIX;
    const int b  = p0 >> 12;
    const int hw0 = p0 & (HW - 1);

    float* xf   = reinterpret_cast<float*>(smem + OFF_XF);
    float* en_s = reinterpret_cast<float*>(smem + OFF_EN);
    float* xn_s = reinterpret_cast<float*>(smem + OFF_XN);
    unsigned long long* best  = reinterpret_cast<unsigned long long*>(smem + OFF_BEST);
    unsigned long long* beste = reinterpret_cast<unsigned long long*>(smem + OFF_BESTE);
    unsigned* cand = reinterpret_cast<unsigned*>(smem + OFF_CAND);
    int* cnt = reinterpret_cast<int*>(smem + OFF_CNT);

    if (tid == 0) *cnt = 0;
    if (tid < TNPIX) {
        best[tid]  = 0xFFFFFFFFFFFFFFFFULL;
        beste[tid] = 0xFFFFFFFFFFFFFFFFULL;
    }
    for (int i = tid; i < K_CODES; i += 256) en_s[i] = g_enorm[i];

    const char* cbbytes = reinterpret_cast<const char*>(g_cbhi);

    // kick off cb chunk 0 load (512 codes x 32 c) while we load the x tile
    {
        uint32_t dbase = sb + OFF_CB;
        #pragma unroll
        for (int i = 0; i < 8; i++) {
            int f = tid + i * 256;            // 0..2047
            int row = f >> 2, seg = f & 3;
            CP_ASYNC16(dbase + row * CB_ROW + seg * 16,
                       cbbytes + (size_t)row * 512 + seg * 16);
        }
        CP_COMMIT();
    }

    // ---- x tile [256 c][64 px]: fp32 + bf16 copies
    {
        const float* xb = x + (size_t)b * C_DIM * HW + hw0;
        #pragma unroll
        for (int it = 0; it < 16; it++) {
            int f = tid + it * 256;
            int row = f >> 4, q = f & 15;
            float4 v = *reinterpret_cast<const float4*>(xb + (size_t)row * HW + q * 4);
            *reinterpret_cast<float4*>(&xf[row * XF_STRIDE + q * 4]) = v;
            __nv_bfloat16 b0 = __float2bfloat16(v.x), b1 = __float2bfloat16(v.y);
            __nv_bfloat16 b2 = __float2bfloat16(v.z), b3 = __float2bfloat16(v.w);
            uint32_t lo = ((uint32_t)__bfloat16_as_ushort(b1) << 16) | __bfloat16_as_ushort(b0);
            uint32_t hi = ((uint32_t)__bfloat16_as_ushort(b3) << 16) | __bfloat16_as_ushort(b2);
            *reinterpret_cast<uint2*>(smem + OFF_XBF + row * 144 + q * 8) = make_uint2(lo, hi);
        }
    }
    __syncthreads();

    // ---- pixel norms: exact reference order
    if (tid < TNPIX) {
        float s = 0.f;
        #pragma unroll 8
        for (int c = 0; c < C_DIM; c++) {
            float v = xf[c * XF_STRIDE + tid];
            s = __fadd_rn(s, __fmul_rn(v, v));
        }
        xn_s[tid] = s;
    }
    __syncthreads();

    const uint32_t a_rowsel = (uint32_t)(lane & 15);
    const uint32_t a_half   = (uint32_t)(lane >> 4);

    float acc[4][8][4];

    // ---- 16 chunks: kt = g>>3 (512-code block), cc = g&7 (32-c slice)
    for (int g = 0; g < 16; g++) {
        const int buf = g & 1;
        if (g < 16 - 1) {
            // prefetch chunk g+1 into other buffer
            int gn = g + 1;
            int ktn = gn >> 3, ccn_ = gn & 7;
            uint32_t dbase = sb + OFF_CB + (buf ^ 1) * CB_BUF;
            const char* srcb = cbbytes + (size_t)(ktn * 512) * 512 + ccn_ * 64;
            #pragma unroll
            for (int i = 0; i < 8; i++) {
                int f = tid + i * 256;
                int row = f >> 2, seg = f & 3;
                CP_ASYNC16(dbase + row * CB_ROW + seg * 16,
                           srcb + (size_t)row * 512 + seg * 16);
            }
            CP_COMMIT();
            CP_WAIT(1);
        } else {
            CP_WAIT(0);
        }
        __syncthreads();   // chunk g visible to all threads

        if ((g & 7) == 0) {
            #pragma unroll
            for (int m = 0; m < 4; m++)
                #pragma unroll
                for (int n = 0; n < 8; n++)
                    #pragma unroll
                    for (int j = 0; j < 4; j++) acc[m][n][j] = 0.f;
        }

        const uint32_t abase = sb + OFF_CB + buf * CB_BUF;
        const int cc = g & 7;
        #pragma unroll
        for (int ccn = 0; ccn < 2; ccn++) {
            uint32_t a[4][4], bfr[4][4];
            #pragma unroll
            for (int m = 0; m < 4; m++) {
                uint32_t addr = abase + (wid * 64 + m * 16 + a_rowsel) * CB_ROW
                              + ccn * 32 + a_half * 16;
                LDSM_X4(a[m], addr);
            }
            #pragma unroll
            for (int np = 0; np < 4; np++) {
                uint32_t addr = sb + OFF_XBF + (cc * 32 + ccn * 16 + a_rowsel) * 144
                              + (np * 16 + a_half * 8) * 2;
                LDSM_X4_T(bfr[np], addr);
            }
            #pragma unroll
            for (int m = 0; m < 4; m++)
                #pragma unroll
                for (int n = 0; n < 8; n++)
                    MMA_BF16(acc[m][n], a[m], bfr[n >> 1][(n & 1) * 2], bfr[n >> 1][(n & 1) * 2 + 1]);
        }

        if ((g & 7) == 7) {
            const int kt = g >> 3;
            // ---- running-min update (thread min -> lane-group shfl -> smem atomicMin)
            #pragma unroll
            for (int n = 0; n < 8; n++)
                #pragma unroll
                for (int co = 0; co < 2; co++) {
                    int px = n * 8 + (lane & 3) * 2 + co;
                    float xn = xn_s[px];
                    unsigned long long kk = 0xFFFFFFFFFFFFFFFFULL;
                    #pragma unroll
                    for (int m = 0; m < 4; m++)
                        #pragma unroll
                        for (int rr = 0; rr < 2; rr++) {
                            int code = kt * 512 + wid * 64 + m * 16 + (lane >> 2) + rr * 8;
                            float s = __fsub_rn(__fadd_rn(xn, en_s[code]),
                                                __fmul_rn(2.f, acc[m][n][rr * 2 + co]));
                            unsigned long long k2 = packkey(s, code);
                            if (k2 < kk) kk = k2;
                        }
                    #pragma unroll
                    for (int d = 4; d < 32; d <<= 1) {
                        unsigned long long o = __shfl_xor_sync(0xFFFFFFFFu, kk, d);
                        if (o < kk) kk = o;
                    }
                    if ((lane >> 2) == 0) atomicMin(&best[px], kk);
                }
            __syncthreads();
            // ---- candidate emission vs running min (superset of final winners)
            #pragma unroll
            for (int n = 0; n < 8; n++)
                #pragma unroll
                for (int co = 0; co < 2; co++) {
                    int px = n * 8 + (lane & 3) * 2 + co;
                    float thr = unpack_score(best[px]) + MARGIN;
                    float xn = xn_s[px];
                    #pragma unroll
                    for (int m = 0; m < 4; m++)
                        #pragma unroll
                        for (int rr = 0; rr < 2; rr++) {
                            int code = kt * 512 + wid * 64 + m * 16 + (lane >> 2) + rr * 8;
                            float s = __fsub_rn(__fadd_rn(xn, en_s[code]),
                                                __fmul_rn(2.f, acc[m][n][rr * 2 + co]));
                            if (s <= thr) {
                                int pos = atomicAdd(cnt, 1);
                                if (pos < CAND_CAP)
                                    cand[pos] = ((unsigned)px << 10) | (unsigned)code;
                            }
                        }
                }
        }
        __syncthreads();   // compute done before this buffer is reloaded
    }

    // ---- exact recheck: sequential fp32 FMA chain, c ascending (reference order)
    int n = *cnt; if (n > CAND_CAP) n = CAND_CAP;
    for (int t = tid; t < n; t += 256) {
        unsigned e = cand[t];
        int px = (int)(e >> 10);
        int k  = (int)(e & 1023u);
        const float* ck = cb + (size_t)k * C_DIM;
        float dot = 0.f;
        #pragma unroll 8
        for (int c = 0; c < C_DIM; c++)
            dot = __fmaf_rn(ck[c], xf[c * XF_STRIDE + px], dot);
        float s = __fsub_rn(__fadd_rn(xn_s[px], en_s[k]), __fmul_rn(2.f, dot));
        atomicMin(&beste[px], packkey(s, k));
    }
    __syncthreads();
    if (tid < TNPIX) g_idx[p0 + tid] = (int)(beste[tid] & 0xFFFFFFFFu);

    // ---- fused outputs (concat mode): idx-as-float + quantized gather
    if (fused_out) {
        if (tid < TNPIX)
            outf[p0 + tid] = (float)(int)(beste[tid] & 0xFFFFFFFFu);
        int px = tid & 63, cg = tid >> 6;          // 4 c-groups of 64
        int k = (int)(beste[px] & 0xFFFFFFFFu);
        const float* ck = cb + (size_t)k * C_DIM + cg * 64;
        float* ob = outq + ((size_t)b * C_DIM + cg * 64) * HW + hw0 + px;
        #pragma unroll 8
        for (int c = 0; c < 64; c++)
            ob[(size_t)c * HW] = __ldg(ck + c);
    }
}

// ---------------------------------------------------------------------------
// 3) standalone outputs for non-concat modes (verified)
// ---------------------------------------------------------------------------
__global__ void gather_kernel(const float* __restrict__ cb, float* __restrict__ q) {
    long long o4 = (long long)blockIdx.x * blockDim.x + threadIdx.x;
    if (o4 >= (long long)(QN / 4)) return;
    int hw = (int)(o4 & (HW - 1));
    long long t = o4 >> 12;
    int c4 = (int)(t & 63);
    int b  = (int)(t >> 6);
    int k = g_idx[b * HW + hw];
    float4 v = __ldg(reinterpret_cast<const float4*>(cb) + (size_t)k * 64 + c4);
    float* qb = q + ((size_t)b * C_DIM + c4 * 4) * HW + hw;
    qb[0]      = v.x;
    qb[HW]     = v.y;
    qb[2 * HW] = v.z;
    qb[3 * HW] = v.w;
}
__global__ void idxi_kernel(int* __restrict__ out) {
    int n = blockIdx.x * blockDim.x + threadIdx.x;
    if (n < NPIX) out[n] = g_idx[n];
}

// ---------------------------------------------------------------------------
extern "C" void kernel_launch(void* const* d_in, const int* in_sizes, int n_in,
                              void* d_out, int out_size) {
    const float* x  = (const float*)d_in[0];   // (32,256,64,64) f32
    const float* cb = (const float*)d_in[1];   // (1024,256) f32

    cudaFuncSetAttribute(vq_hmma_kernel,
                         cudaFuncAttributeMaxDynamicSharedMemorySize, SMEM_TOTAL);

    prep_kernel<<<1028, 256>>>(cb);

    if (out_size >= NPIX + QN) {
        vq_hmma_kernel<<<NPIX / TNPIX, 256, SMEM_TOTAL>>>(
            x, cb, (float*)d_out, (float*)d_out + NPIX, 1);
    } else if (out_size >= QN) {
        vq_hmma_kernel<<<NPIX / TNPIX, 256, SMEM_TOTAL>>>(x, cb, nullptr, nullptr, 0);
        gather_kernel<<<QN / 4 / 256, 256>>>(cb, (float*)d_out);
    } else {
        vq_hmma_kernel<<<NPIX / TNPIX, 256, SMEM_TOTAL>>>(x, cb, nullptr, nullptr, 0);
        idxi_kernel<<<NPIX / 256, 256>>>((int*)d_out);
    }
}